// round 5
// baseline (speedup 1.0000x reference)
#include <cuda_runtime.h>
#include <cstdint>

#define N_NODES 100000
#define N_EDGES 3200000
#define IN_F    128

// ---------------- scratch (no allocations allowed) ----------------
__device__ float g_yr[N_NODES * 32];    // [n][0:16]=y (lin_l transform), [n][16:32]=r (lin_r) ; later a|b for edge MLP
__device__ float g_agg[N_NODES * 16];   // neighbor-sum accumulator
__device__ float g_cnt[N_NODES];        // in-degree (float)
__device__ float g_h[N_NODES * 16];     // hidden activations (h1 then h2)

// ---------------- kernels ----------------

__global__ void k_zero() {
    int i = blockIdx.x * blockDim.x + threadIdx.x;
    if (i < N_NODES * 16) g_agg[i] = 0.f;
    if (i < N_NODES)      g_cnt[i] = 0.f;
}

// y|r = x @ [w1_l | w1_r]   (128 -> 32), weights staged in shared, broadcast reads
__global__ void k_gemm_in(const float* __restrict__ x,
                          const float* __restrict__ wl,
                          const float* __restrict__ wr) {
    __shared__ float sw[IN_F * 32];
    for (int i = threadIdx.x; i < IN_F * 32; i += blockDim.x) {
        int k = i >> 5, c = i & 31;
        sw[i] = (c < 16) ? wl[k * 16 + c] : wr[k * 16 + (c - 16)];
    }
    __syncthreads();
    int n = blockIdx.x * blockDim.x + threadIdx.x;
    if (n >= N_NODES) return;

    float acc[32];
#pragma unroll
    for (int j = 0; j < 32; j++) acc[j] = 0.f;

    const float4* xr  = (const float4*)(x + (size_t)n * IN_F);
    const float4* sw4 = (const float4*)sw;

#pragma unroll 4
    for (int k4 = 0; k4 < IN_F / 4; k4++) {
        float4 xv = __ldg(xr + k4);
        float xs[4] = {xv.x, xv.y, xv.z, xv.w};
#pragma unroll
        for (int i = 0; i < 4; i++) {
            float xk = xs[i];
#pragma unroll
            for (int j = 0; j < 8; j++) {
                float4 w = sw4[(k4 * 4 + i) * 8 + j];   // uniform addr -> smem broadcast
                acc[4 * j + 0] = fmaf(xk, w.x, acc[4 * j + 0]);
                acc[4 * j + 1] = fmaf(xk, w.y, acc[4 * j + 1]);
                acc[4 * j + 2] = fmaf(xk, w.z, acc[4 * j + 2]);
                acc[4 * j + 3] = fmaf(xk, w.w, acc[4 * j + 3]);
            }
        }
    }
    float4* o = (float4*)(g_yr + (size_t)n * 32);
#pragma unroll
    for (int j = 0; j < 8; j++)
        o[j] = make_float4(acc[4 * j], acc[4 * j + 1], acc[4 * j + 2], acc[4 * j + 3]);
}

// generic 16 -> 32 transform from g_h into g_yr.
// sw[k][c] = (c<16) ? wa[k][c] : wb[k+offB][c-16]; optional bias added to cols 0..15.
__global__ void k_gemm16(const float* __restrict__ wa,
                         const float* __restrict__ wb,
                         const float* __restrict__ bias,
                         int offB) {
    __shared__ float sw[16 * 32];
    for (int i = threadIdx.x; i < 16 * 32; i += blockDim.x) {
        int k = i >> 5, c = i & 31;
        sw[i] = (c < 16) ? wa[k * 16 + c] : wb[(k + offB) * 16 + (c - 16)];
    }
    __syncthreads();
    int n = blockIdx.x * blockDim.x + threadIdx.x;
    if (n >= N_NODES) return;

    float acc[32];
#pragma unroll
    for (int j = 0; j < 32; j++) acc[j] = 0.f;

    const float4* hr = (const float4*)(g_h + (size_t)n * 16);
    float4 hv[4];
#pragma unroll
    for (int q = 0; q < 4; q++) hv[q] = hr[q];
    float hrow[16] = {hv[0].x, hv[0].y, hv[0].z, hv[0].w,
                      hv[1].x, hv[1].y, hv[1].z, hv[1].w,
                      hv[2].x, hv[2].y, hv[2].z, hv[2].w,
                      hv[3].x, hv[3].y, hv[3].z, hv[3].w};

    const float4* sw4 = (const float4*)sw;
#pragma unroll
    for (int k = 0; k < 16; k++) {
        float xk = hrow[k];
#pragma unroll
        for (int j = 0; j < 8; j++) {
            float4 w = sw4[k * 8 + j];
            acc[4 * j + 0] = fmaf(xk, w.x, acc[4 * j + 0]);
            acc[4 * j + 1] = fmaf(xk, w.y, acc[4 * j + 1]);
            acc[4 * j + 2] = fmaf(xk, w.z, acc[4 * j + 2]);
            acc[4 * j + 3] = fmaf(xk, w.w, acc[4 * j + 3]);
        }
    }
    if (bias) {
#pragma unroll
        for (int j = 0; j < 16; j++) acc[j] += __ldg(bias + j);
    }
    float4* o = (float4*)(g_yr + (size_t)n * 32);
#pragma unroll
    for (int j = 0; j < 8; j++)
        o[j] = make_float4(acc[4 * j], acc[4 * j + 1], acc[4 * j + 2], acc[4 * j + 3]);
}

// edge scatter: 4 threads per edge, each does one 16B vector red to g_agg[dst]
__global__ void k_scatter(const int* __restrict__ ei, int addCnt) {
    int t = blockIdx.x * blockDim.x + threadIdx.x;
    if (t >= N_EDGES * 4) return;
    int e = t >> 2, c = t & 3;
    int s = __ldg(ei + e);
    int d = __ldg(ei + N_EDGES + e);
    float4 v = *(const float4*)(g_yr + (size_t)s * 32 + 4 * c);  // y part (cols 0..15)
    float* p = g_agg + (size_t)d * 16 + 4 * c;
    asm volatile("red.global.add.v4.f32 [%0], {%1,%2,%3,%4};"
                 :: "l"(p), "f"(v.x), "f"(v.y), "f"(v.z), "f"(v.w) : "memory");
    if (addCnt && c == 0) atomicAdd(g_cnt + d, 1.0f);
}

// h = relu(agg / max(cnt,1) + b_l + r) ; optionally re-zero agg for next layer
__global__ void k_combine(const float* __restrict__ bl, int zeroAgg) {
    int i = blockIdx.x * blockDim.x + threadIdx.x;
    if (i >= N_NODES * 16) return;
    int n = i >> 4, j = i & 15;
    float cnt = fmaxf(g_cnt[n], 1.0f);
    float v = g_agg[i] / cnt + __ldg(bl + j) + g_yr[(size_t)n * 32 + 16 + j];
    g_h[i] = fmaxf(v, 0.f);
    if (zeroAgg) g_agg[i] = 0.f;
}

// per edge: z = relu(a[src] + b[dst]) ; o = z @ fc2 + fc2_b ; log_softmax
__global__ void k_edge(const int* __restrict__ ei,
                       const float* __restrict__ fc2w,
                       const float* __restrict__ fc2b,
                       float* __restrict__ out) {
    __shared__ float sf[34];
    if (threadIdx.x < 32) sf[threadIdx.x] = fc2w[threadIdx.x];
    if (threadIdx.x < 2)  sf[32 + threadIdx.x] = fc2b[threadIdx.x];
    __syncthreads();
    int e = blockIdx.x * blockDim.x + threadIdx.x;
    if (e >= N_EDGES) return;
    int s = __ldg(ei + e);
    int d = __ldg(ei + N_EDGES + e);
    const float4* ap = (const float4*)(g_yr + (size_t)s * 32);       // a = h_s@fc1_top + fc1_b
    const float4* bp = (const float4*)(g_yr + (size_t)d * 32 + 16);  // b = h_d@fc1_bot
    float o0 = sf[32], o1 = sf[33];
#pragma unroll
    for (int q = 0; q < 4; q++) {
        float4 a = ap[q];
        float4 b = bp[q];
        float z0 = fmaxf(a.x + b.x, 0.f);
        float z1 = fmaxf(a.y + b.y, 0.f);
        float z2 = fmaxf(a.z + b.z, 0.f);
        float z3 = fmaxf(a.w + b.w, 0.f);
        int j = q * 4;
        o0 = fmaf(z0, sf[(j + 0) * 2 + 0], o0);  o1 = fmaf(z0, sf[(j + 0) * 2 + 1], o1);
        o0 = fmaf(z1, sf[(j + 1) * 2 + 0], o0);  o1 = fmaf(z1, sf[(j + 1) * 2 + 1], o1);
        o0 = fmaf(z2, sf[(j + 2) * 2 + 0], o0);  o1 = fmaf(z2, sf[(j + 2) * 2 + 1], o1);
        o0 = fmaf(z3, sf[(j + 3) * 2 + 0], o0);  o1 = fmaf(z3, sf[(j + 3) * 2 + 1], o1);
    }
    float m = fmaxf(o0, o1);
    float l = m + __logf(__expf(o0 - m) + __expf(o1 - m));
    ((float2*)out)[e] = make_float2(o0 - l, o1 - l);
}

// ---------------- launch ----------------

extern "C" void kernel_launch(void* const* d_in, const int* in_sizes, int n_in,
                              void* d_out, int out_size) {
    const float* x    = (const float*)d_in[0];
    const int*   ei   = (const int*)  d_in[1];
    const float* w1l  = (const float*)d_in[2];
    const float* b1l  = (const float*)d_in[3];
    const float* w1r  = (const float*)d_in[4];
    const float* w2l  = (const float*)d_in[5];
    const float* b2l  = (const float*)d_in[6];
    const float* w2r  = (const float*)d_in[7];
    const float* fc1w = (const float*)d_in[8];
    const float* fc1b = (const float*)d_in[9];
    const float* fc2w = (const float*)d_in[10];
    const float* fc2b = (const float*)d_in[11];
    float* out = (float*)d_out;

    const int TB = 256;
    int gN16 = (N_NODES * 16 + TB - 1) / TB;
    int gN   = (N_NODES + 127) / 128;
    int gE4  = (N_EDGES * 4 + TB - 1) / TB;
    int gE   = (N_EDGES + TB - 1) / TB;

    // layer 1
    k_zero<<<gN16, TB>>>();
    k_gemm_in<<<gN, 128>>>(x, w1l, w1r);
    k_scatter<<<gE4, TB>>>(ei, 1);
    k_combine<<<gN16, TB>>>(b1l, 1);   // writes h1, re-zeros agg
    // layer 2
    k_gemm16<<<gN, 128>>>(w2l, w2r, nullptr, 0);
    k_scatter<<<gE4, TB>>>(ei, 0);
    k_combine<<<gN16, TB>>>(b2l, 0);   // writes h2
    // edge MLP precompute: a|b = h2 @ [fc1_top | fc1_bot] (+fc1_b on a)
    k_gemm16<<<gN, 128>>>(fc1w, fc1w, fc1b, 16);
    // per-edge head + log_softmax
    k_edge<<<gE, TB>>>(ei, fc2w, fc2b, out);
}